// round 1
// baseline (speedup 1.0000x reference)
#include <cuda_runtime.h>

#define TPB_TOPK 512
#define NBINS    16384
#define CAP      4096
#define NK       100
#define BATCH    64
#define HW       65536
#define D2R      0.017453292519943295f

// scratch: [tensor][batch][k][xy]
__device__ float g_xy[2][BATCH][NK][2];
__device__ float g_part[BATCH][2];

// order-preserving float->uint key (ascending)
__device__ __forceinline__ unsigned fkey(float f) {
    unsigned u = __float_as_uint(f);
    unsigned m = (unsigned)((int)u >> 31);      // 0xFFFFFFFF if negative
    return u ^ (m | 0x80000000u);
}

// warp-aggregated histogram add, all lanes active
__device__ __forceinline__ void hadd(unsigned* hist, unsigned bin) {
    unsigned mm = __match_any_sync(0xffffffffu, bin);
    if ((threadIdx.x & 31) == (unsigned)(__ffs(mm) - 1))
        atomicAdd(&hist[bin], (unsigned)__popc(mm));
}

// warp-aggregated histogram add under a predicate
__device__ __forceinline__ void hadd_pred(unsigned* hist, unsigned bin, bool pred) {
    unsigned am = __ballot_sync(0xffffffffu, pred);
    if (pred) {
        unsigned mm = __match_any_sync(am, bin);
        if ((threadIdx.x & 31) == (unsigned)(__ffs(mm) - 1))
            atomicAdd(&hist[bin], (unsigned)__popc(mm));
    }
}

// Find bin b such that (count in bins > b) < K <= (count in bins >= b).
// Writes *s_bin = b, *s_above = count strictly above. Block-collective.
__device__ void suffix_find(const unsigned* hist, int NB, unsigned K,
                            unsigned* s_warpsum, unsigned* s_bin, unsigned* s_above) {
    int tid  = threadIdx.x;
    int lane = tid & 31, warp = tid >> 5;
    int bpt  = (NB + TPB_TOPK - 1) / TPB_TOPK;
    int base = tid * bpt;
    unsigned p = 0;
    for (int j = 0; j < bpt; j++) {
        int b = base + j;
        if (b < NB) p += hist[b];
    }
    // inclusive suffix scan within warp (sum over lanes >= lane)
    unsigned v = p;
    for (int d = 1; d < 32; d <<= 1) {
        unsigned o = __shfl_down_sync(0xffffffffu, v, d);
        if (lane + d < 32) v += o;
    }
    if (lane == 0) s_warpsum[warp] = v;
    __syncthreads();
    unsigned add = 0;
    for (int w = warp + 1; w < TPB_TOPK / 32; w++) add += s_warpsum[w];
    unsigned sAfter = (v - p) + add;   // count in threads strictly after tid
    if (sAfter < K && sAfter + p >= K) {
        unsigned cum = sAfter;
        for (int j = bpt - 1; j >= 0; j--) {
            int b = base + j;
            if (b >= NB) continue;
            unsigned h = hist[b];
            if (cum + h >= K) { *s_bin = (unsigned)b; *s_above = cum; break; }
            cum += h;
        }
    }
    __syncthreads();
}

extern __shared__ unsigned char s_raw[];

__global__ void __launch_bounds__(TPB_TOPK)
topk_kernel(const float* __restrict__ hm_p, const float* __restrict__ hm_t) {
    unsigned* hist = (unsigned*)s_raw;
    // candidate buffer aliases hist region: used only after all hist reads are done
    unsigned long long* cand = (unsigned long long*)s_raw;
    __shared__ unsigned s_warpsum[TPB_TOPK / 32];
    __shared__ unsigned s_bin, s_above, s_cnt;

    int tid    = threadIdx.x;
    int bb     = blockIdx.x;
    int tensor = bb >> 6;
    int batch  = bb & 63;
    const float4* src4 =
        (const float4*)((tensor ? hm_t : hm_p) + (size_t)batch * HW);

    // ---- Level 0 histogram: top 14 bits of key ----
    for (int i = tid; i < NBINS; i += TPB_TOPK) hist[i] = 0;
    __syncthreads();
    for (int i = tid; i < HW / 4; i += TPB_TOPK) {
        float4 f = src4[i];
        hadd(hist, fkey(f.x) >> 18);
        hadd(hist, fkey(f.y) >> 18);
        hadd(hist, fkey(f.z) >> 18);
        hadd(hist, fkey(f.w) >> 18);
    }
    __syncthreads();
    suffix_find(hist, NBINS, NK, s_warpsum, &s_bin, &s_above);
    unsigned b0 = s_bin, a0 = s_above;
    unsigned M  = a0 + hist[b0];
    unsigned selP = b0;
    int      selS = 18;

    if (M > CAP) {
        // ---- Level 1: next 14 bits, restricted to bin b0 ----
        __syncthreads();
        for (int i = tid; i < NBINS; i += TPB_TOPK) hist[i] = 0;
        __syncthreads();
        for (int i = tid; i < HW / 4; i += TPB_TOPK) {
            float4 f = src4[i];
            unsigned u[4] = {fkey(f.x), fkey(f.y), fkey(f.z), fkey(f.w)};
#pragma unroll
            for (int c = 0; c < 4; c++)
                hadd_pred(hist, (u[c] >> 4) & 0x3FFFu, (u[c] >> 18) == b0);
        }
        __syncthreads();
        suffix_find(hist, NBINS, NK - a0, s_warpsum, &s_bin, &s_above);
        unsigned b1 = s_bin, a1 = s_above;
        M    = a0 + a1 + hist[b1];
        selP = (b0 << 14) | b1;
        selS = 4;
        if (M > CAP) {
            // ---- Level 2: last 4 bits (exact key threshold) ----
            __syncthreads();
            if (tid < 16) hist[tid] = 0;
            __syncthreads();
            for (int i = tid; i < HW / 4; i += TPB_TOPK) {
                float4 f = src4[i];
                unsigned u[4] = {fkey(f.x), fkey(f.y), fkey(f.z), fkey(f.w)};
#pragma unroll
                for (int c = 0; c < 4; c++)
                    hadd_pred(hist, u[c] & 0xFu, (u[c] >> 4) == selP);
            }
            __syncthreads();
            suffix_find(hist, 16, NK - a0 - a1, s_warpsum, &s_bin, &s_above);
            unsigned b2 = s_bin;
            M    = a0 + a1 + s_above + hist[b2];
            selP = (selP << 4) | b2;
            selS = 0;
        }
    }

    // ---- Collection pass (cand aliases hist; all hist reads are complete) ----
    if (tid == 0) s_cnt = 0;
    __syncthreads();
    for (int i = tid; i < HW / 4; i += TPB_TOPK) {
        float4 f = src4[i];
        unsigned u[4] = {fkey(f.x), fkey(f.y), fkey(f.z), fkey(f.w)};
#pragma unroll
        for (int c = 0; c < 4; c++) {
            if ((u[c] >> selS) >= selP) {
                unsigned pos = atomicAdd(&s_cnt, 1u);
                if (pos < CAP) {
                    unsigned idx = (unsigned)(i * 4 + c);
                    cand[pos] = ((unsigned long long)u[c] << 16) |
                                (unsigned long long)(65535u - idx);
                }
            }
        }
    }
    __syncthreads();
    unsigned Mc = s_cnt < (unsigned)CAP ? s_cnt : (unsigned)CAP;
    int P2 = 128;
    while (P2 < (int)Mc) P2 <<= 1;
    for (int i = (int)Mc + tid; i < P2; i += TPB_TOPK) cand[i] = 0ULL;
    __syncthreads();

    // bitonic sort descending by (key, 65535-idx) => stable jax tie order
    for (int k = 2; k <= P2; k <<= 1) {
        for (int j = k >> 1; j > 0; j >>= 1) {
            for (int i = tid; i < P2; i += TPB_TOPK) {
                int ixj = i ^ j;
                if (ixj > i) {
                    unsigned long long a = cand[i], b = cand[ixj];
                    bool up = (i & k) == 0;
                    bool sw = up ? (a < b) : (a > b);
                    if (sw) { cand[i] = b; cand[ixj] = a; }
                }
            }
            __syncthreads();
        }
    }

    if (tid < NK) {
        unsigned idx = 65535u - (unsigned)(cand[tid] & 0xFFFFULL);
        g_xy[tensor][batch][tid][0] = (float)(idx & 255u);   // x
        g_xy[tensor][batch][tid][1] = (float)(idx >> 8);     // y
    }
}

__device__ __forceinline__ float gwd_one(float xp, float yp, float wp, float hp, float ap,
                                         float xt, float yt, float wt, float ht, float at) {
    wp = fminf(fmaxf(wp, 1e-7f), 1e7f);
    hp = fminf(fmaxf(hp, 1e-7f), 1e7f);
    wt = fminf(fmaxf(wt, 1e-7f), 1e7f);
    ht = fminf(fmaxf(ht, 1e-7f), 1e7f);
    float sp, cp, st, ct;
    sincosf(ap * D2R, &sp, &cp);
    sincosf(at * D2R, &st, &ct);
    float s1p = 0.5f * wp, s2p = 0.5f * hp, s1t = 0.5f * wt, s2t = 0.5f * ht;
    float dx = xp - xt, dy = yp - yt;
    float xyd = dx * dx + dy * dy;
    float q1p = s1p * s1p, q2p = s2p * s2p, q1t = s1t * s1t, q2t = s2t * s2t;
    float Ap = cp * cp * q1p + sp * sp * q2p;
    float Bp = cp * sp * (q1p - q2p);
    float Cp = sp * sp * q1p + cp * cp * q2p;
    float At = ct * ct * q1t + st * st * q2t;
    float Bt = ct * st * (q1t - q2t);
    float Ct = st * st * q1t + ct * ct * q2t;
    float whr  = q1p + q2p + q1t + q2t;
    float tr   = Ap * At + 2.f * Bp * Bt + Cp * Ct;
    float dets = s1p * s2p * s1t * s2t;
    whr -= 2.f * sqrtf(fmaxf(tr + 2.f * dets, 0.f));
    float d = fmaxf(xyd + whr, 0.f);
    d = log1pf(d);
    return 1.f - 1.f / (1.f + d);
}

__global__ void __launch_bounds__(128)
loss_kernel(const float* __restrict__ ab_p, const float* __restrict__ ang_p,
            const float* __restrict__ ab_t, const float* __restrict__ ang_t,
            const int* __restrict__ ind, const int* __restrict__ msk) {
    int b = blockIdx.x, t = threadIdx.x;
    float loss = 0.f, mval = 0.f;
    if (t < NK) {
        int r   = b * NK + t;
        float m = (float)msk[r];
        int id  = ind[r];
        size_t ab_base = (size_t)b * (2 * HW);
        float wp = ab_p[ab_base + id] * 2.f * m;
        float hp = ab_p[ab_base + HW + id] * 2.f * m;
        float ap = (ang_p[(size_t)b * HW + id] - 90.f) * m;
        float xp = g_xy[0][b][t][0] * m, yp = g_xy[0][b][t][1] * m;
        float xt = g_xy[1][b][t][0] * m, yt = g_xy[1][b][t][1] * m;
        float wt = ab_t[r * 2] * 2.f * m, ht = ab_t[r * 2 + 1] * 2.f * m;
        float at = (ang_t[r] - 90.f) * m;
        loss = gwd_one(xp, yp, wp, hp, ap, xt, yt, wt, ht, at);
        mval = m;
    }
    for (int d = 16; d > 0; d >>= 1) {
        loss += __shfl_down_sync(0xffffffffu, loss, d);
        mval += __shfl_down_sync(0xffffffffu, mval, d);
    }
    __shared__ float rl[4], rm[4];
    if ((t & 31) == 0) { rl[t >> 5] = loss; rm[t >> 5] = mval; }
    __syncthreads();
    if (t == 0) {
        g_part[b][0] = rl[0] + rl[1] + rl[2] + rl[3];
        g_part[b][1] = rm[0] + rm[1] + rm[2] + rm[3];
    }
}

__global__ void finalize_kernel(float* __restrict__ out) {
    int t = threadIdx.x;  // 64 threads
    float l = g_part[t][0], m = g_part[t][1];
    for (int d = 16; d > 0; d >>= 1) {
        l += __shfl_down_sync(0xffffffffu, l, d);
        m += __shfl_down_sync(0xffffffffu, m, d);
    }
    __shared__ float sl[2], sm2[2];
    if ((t & 31) == 0) { sl[t >> 5] = l; sm2[t >> 5] = m; }
    __syncthreads();
    if (t == 0) out[0] = (sl[0] + sl[1]) / ((sm2[0] + sm2[1]) + 1e-8f);
}

extern "C" void kernel_launch(void* const* d_in, const int* in_sizes, int n_in,
                              void* d_out, int out_size) {
    const float* hm_p  = (const float*)d_in[0];
    const float* ab_p  = (const float*)d_in[1];
    const float* ang_p = (const float*)d_in[2];
    const float* hm_t  = (const float*)d_in[3];
    const float* ab_t  = (const float*)d_in[4];
    const float* ang_t = (const float*)d_in[5];
    const int*   ind   = (const int*)d_in[6];
    const int*   msk   = (const int*)d_in[7];
    float*       out   = (float*)d_out;

    const int smem = NBINS * 4;  // cand buffer aliases the histogram region
    cudaFuncSetAttribute(topk_kernel, cudaFuncAttributeMaxDynamicSharedMemorySize, smem);
    topk_kernel<<<2 * BATCH, TPB_TOPK, smem>>>(hm_p, hm_t);
    loss_kernel<<<BATCH, 128>>>(ab_p, ang_p, ab_t, ang_t, ind, msk);
    finalize_kernel<<<1, 64>>>(out);
}

// round 2
// speedup vs baseline: 1.2667x; 1.2667x over previous
#include <cuda_runtime.h>

#define HW     65536
#define BATCH  64
#define NTB    128           // 2 tensors x 64 batches
#define NK     100
#define SHIFT  19
#define NB2    8192          // 2^13 coarse bins on top 13 key bits
#define CAP    4096
#define KEEPC  2048
#define SLICES 4
#define TPB    512
#define D2R    0.017453292519943295f

__device__ unsigned           g_hist[NTB * NB2];
__device__ unsigned           g_cnt[NTB];
__device__ unsigned long long g_cand[NTB][CAP];
__device__ float2             g_sel[NTB];          // x = float threshold, y = bitcast(b0)
__device__ float              g_xy[2][BATCH][NK][2];
__device__ float              g_part[BATCH][2];

// order-preserving float->uint key (ascending)
__device__ __forceinline__ unsigned fkey(float f) {
    unsigned u = __float_as_uint(f);
    return u ^ ((unsigned)((int)u >> 31) | 0x80000000u);
}
__device__ __forceinline__ float inv_fkey(unsigned k) {
    unsigned u = (k & 0x80000000u) ? (k ^ 0x80000000u) : ~k;
    return __uint_as_float(u);
}

// Find bin b with (count in bins > b) < K <= (count in bins >= b). Block-collective.
template <int TPBX>
__device__ void suffix_find(const unsigned* hist, int NB, unsigned K,
                            unsigned* s_ws, unsigned* s_bin, unsigned* s_above) {
    int tid  = threadIdx.x;
    int lane = tid & 31, warp = tid >> 5;
    int bpt  = (NB + TPBX - 1) / TPBX;
    int base = tid * bpt;
    unsigned p = 0;
    for (int j = 0; j < bpt; j++) {
        int b = base + j;
        if (b < NB) p += hist[b];
    }
    unsigned v = p;
    for (int d = 1; d < 32; d <<= 1) {
        unsigned o = __shfl_down_sync(0xffffffffu, v, d);
        if (lane + d < 32) v += o;
    }
    if (lane == 0) s_ws[warp] = v;
    __syncthreads();
    unsigned add = 0;
    for (int w = warp + 1; w < TPBX / 32; w++) add += s_ws[w];
    unsigned sAfter = (v - p) + add;
    if (sAfter < K && sAfter + p >= K) {
        unsigned cum = sAfter;
        for (int j = bpt - 1; j >= 0; j--) {
            int b = base + j;
            if (b >= NB) continue;
            unsigned h = hist[b];
            if (cum + h >= K) { *s_bin = (unsigned)b; *s_above = cum; break; }
            cum += h;
        }
    }
    __syncthreads();
}

__device__ __forceinline__ const float4* slice_ptr(const float* hm_p, const float* hm_t,
                                                   int tb, int slice) {
    const float* base = (tb >= BATCH) ? hm_t + (size_t)(tb - BATCH) * HW
                                      : hm_p + (size_t)tb * HW;
    return (const float4*)base + slice * (HW / 4 / SLICES);
}

__global__ void __launch_bounds__(TPB) zero_kernel() {
    int i = blockIdx.x * TPB + threadIdx.x;   // 512 blocks x 512 = NTB*NB2/4
    ((uint4*)g_hist)[i] = make_uint4(0, 0, 0, 0);
}

__global__ void __launch_bounds__(TPB) hist_kernel(const float* __restrict__ hm_p,
                                                   const float* __restrict__ hm_t) {
    __shared__ unsigned sh[NB2];
    int tid = threadIdx.x;
    int tb = blockIdx.x >> 2, slice = blockIdx.x & 3;
    const float4* src = slice_ptr(hm_p, hm_t, tb, slice);
    for (int i = tid; i < NB2; i += TPB) sh[i] = 0;
    __syncthreads();
#pragma unroll
    for (int j = 0; j < HW / (4 * SLICES * TPB); j++) {   // 8 iters
        float4 f = src[tid + j * TPB];
        atomicAdd(&sh[fkey(f.x) >> SHIFT], 1u);
        atomicAdd(&sh[fkey(f.y) >> SHIFT], 1u);
        atomicAdd(&sh[fkey(f.z) >> SHIFT], 1u);
        atomicAdd(&sh[fkey(f.w) >> SHIFT], 1u);
    }
    __syncthreads();
    unsigned* gh = g_hist + tb * NB2;
    for (int i = tid; i < NB2; i += TPB) {
        unsigned v = sh[i];
        if (v) atomicAdd(&gh[i], v);
    }
}

__global__ void __launch_bounds__(TPB) select_kernel() {
    __shared__ unsigned sh[NB2];
    __shared__ unsigned s_ws[TPB / 32];
    __shared__ unsigned s_bin, s_above;
    int tb = blockIdx.x, tid = threadIdx.x;
    const unsigned* gh = g_hist + tb * NB2;
    for (int i = tid; i < NB2; i += TPB) sh[i] = gh[i];
    if (tid == 0) g_cnt[tb] = 0;              // reset for collect pass
    __syncthreads();
    suffix_find<TPB>(sh, NB2, NK, s_ws, &s_bin, &s_above);
    if (tid == 0) {
        unsigned b0 = s_bin;
        g_sel[tb] = make_float2(inv_fkey(b0 << SHIFT), __uint_as_float(b0));
    }
}

__global__ void __launch_bounds__(TPB) collect_kernel(const float* __restrict__ hm_p,
                                                      const float* __restrict__ hm_t) {
    int tid = threadIdx.x, lane = tid & 31;
    int tb = blockIdx.x >> 2, slice = blockIdx.x & 3;
    const float4* src = slice_ptr(hm_p, hm_t, tb, slice);
    float thresh = g_sel[tb].x;
#pragma unroll
    for (int j = 0; j < HW / (4 * SLICES * TPB); j++) {
        int i4 = tid + j * TPB;
        float4 f = src[i4];
        float v[4] = {f.x, f.y, f.z, f.w};
#pragma unroll
        for (int c = 0; c < 4; c++) {
            bool p = v[c] >= thresh;
            unsigned bal = __ballot_sync(0xffffffffu, p);
            if (bal) {
                int leader = __ffs(bal) - 1;
                unsigned basep = 0;
                if (lane == leader) basep = atomicAdd(&g_cnt[tb], (unsigned)__popc(bal));
                basep = __shfl_sync(0xffffffffu, basep, leader);
                if (p) {
                    unsigned pos = basep + __popc(bal & ((1u << lane) - 1));
                    if (pos < CAP) {
                        unsigned idx = (unsigned)((slice * (HW / 4 / SLICES) + i4) * 4 + c);
                        g_cand[tb][pos] = ((unsigned long long)fkey(v[c]) << 16) |
                                          (unsigned long long)(65535u - idx);
                    }
                }
            }
        }
    }
}

extern __shared__ unsigned long long dyn_smem[];

__global__ void __launch_bounds__(256) refine_kernel() {
    unsigned long long* sc = dyn_smem;          // CAP entries
    unsigned long long* sk = dyn_smem + CAP;    // KEEPC entries
    __shared__ unsigned rh[256];
    __shared__ unsigned s_ws[8];
    __shared__ unsigned s_bin, s_above, s_a0l, s_kcnt;
    int tb = blockIdx.x, tid = threadIdx.x, lane = tid & 31, warp = tid >> 5;
    unsigned Mc = g_cnt[tb]; if (Mc > CAP) Mc = CAP;
    unsigned b0 = __float_as_uint(g_sel[tb].y);
    rh[tid] = 0;
    for (unsigned i = tid; i < Mc; i += 256) sc[i] = g_cand[tb][i];
    __syncthreads();

    // refined 256-bin histogram on bits [SHIFT-8, SHIFT) within bin b0
    unsigned a0l = 0;
    for (unsigned i = tid; i < Mc; i += 256) {
        unsigned key = (unsigned)(sc[i] >> 16);
        if ((key >> SHIFT) > b0) a0l++;
        else atomicAdd(&rh[(key >> (SHIFT - 8)) & 255u], 1u);
    }
    for (int d = 16; d > 0; d >>= 1) a0l += __shfl_down_sync(0xffffffffu, a0l, d);
    if (lane == 0) s_ws[warp] = a0l;
    __syncthreads();
    if (tid == 0) { unsigned s = 0; for (int w = 0; w < 8; w++) s += s_ws[w]; s_a0l = s; }
    __syncthreads();
    unsigned a0v = s_a0l;
    suffix_find<256>(rh, 256, NK - a0v, s_ws, &s_bin, &s_above);
    unsigned r0 = s_bin;

    if (tid == 0) s_kcnt = 0;
    __syncthreads();
    for (unsigned i = tid; i < Mc; i += 256) {
        unsigned key = (unsigned)(sc[i] >> 16);
        bool keep = ((key >> SHIFT) > b0) || (((key >> (SHIFT - 8)) & 255u) >= r0);
        if (keep) {
            unsigned p = atomicAdd(&s_kcnt, 1u);
            if (p < KEEPC) sk[p] = sc[i];
        }
    }
    __syncthreads();
    unsigned Mk = s_kcnt; if (Mk > KEEPC) Mk = KEEPC;
    unsigned P2 = 128; while (P2 < Mk) P2 <<= 1;
    for (unsigned i = Mk + tid; i < P2; i += 256) sk[i] = 0ULL;
    __syncthreads();

    // bitonic sort descending on (key, 65535-idx) => jax stable tie order
    for (unsigned k = 2; k <= P2; k <<= 1) {
        for (unsigned j = k >> 1; j > 0; j >>= 1) {
            for (unsigned i = tid; i < P2; i += 256) {
                unsigned ixj = i ^ j;
                if (ixj > i) {
                    unsigned long long a = sk[i], b = sk[ixj];
                    bool up = (i & k) == 0;
                    if (up ? (a < b) : (a > b)) { sk[i] = b; sk[ixj] = a; }
                }
            }
            __syncthreads();
        }
    }

    if (tid < NK) {
        unsigned idx = 65535u - (unsigned)(sk[tid] & 0xFFFFULL);
        int tensor = (tb >= BATCH) ? 1 : 0;
        g_xy[tensor][tb & 63][tid][0] = (float)(idx & 255u);
        g_xy[tensor][tb & 63][tid][1] = (float)(idx >> 8);
    }
}

__device__ __forceinline__ float gwd_one(float xp, float yp, float wp, float hp, float ap,
                                         float xt, float yt, float wt, float ht, float at) {
    wp = fminf(fmaxf(wp, 1e-7f), 1e7f);
    hp = fminf(fmaxf(hp, 1e-7f), 1e7f);
    wt = fminf(fmaxf(wt, 1e-7f), 1e7f);
    ht = fminf(fmaxf(ht, 1e-7f), 1e7f);
    float sp, cp, st, ct;
    sincosf(ap * D2R, &sp, &cp);
    sincosf(at * D2R, &st, &ct);
    float s1p = 0.5f * wp, s2p = 0.5f * hp, s1t = 0.5f * wt, s2t = 0.5f * ht;
    float dx = xp - xt, dy = yp - yt;
    float xyd = dx * dx + dy * dy;
    float q1p = s1p * s1p, q2p = s2p * s2p, q1t = s1t * s1t, q2t = s2t * s2t;
    float Ap = cp * cp * q1p + sp * sp * q2p;
    float Bp = cp * sp * (q1p - q2p);
    float Cp = sp * sp * q1p + cp * cp * q2p;
    float At = ct * ct * q1t + st * st * q2t;
    float Bt = ct * st * (q1t - q2t);
    float Ct = st * st * q1t + ct * ct * q2t;
    float whr  = q1p + q2p + q1t + q2t;
    float tr   = Ap * At + 2.f * Bp * Bt + Cp * Ct;
    float dets = s1p * s2p * s1t * s2t;
    whr -= 2.f * sqrtf(fmaxf(tr + 2.f * dets, 0.f));
    float d = fmaxf(xyd + whr, 0.f);
    d = log1pf(d);
    return 1.f - 1.f / (1.f + d);
}

__global__ void __launch_bounds__(128)
loss_kernel(const float* __restrict__ ab_p, const float* __restrict__ ang_p,
            const float* __restrict__ ab_t, const float* __restrict__ ang_t,
            const int* __restrict__ ind, const int* __restrict__ msk) {
    int b = blockIdx.x, t = threadIdx.x;
    float loss = 0.f, mval = 0.f;
    if (t < NK) {
        int r   = b * NK + t;
        float m = (float)msk[r];
        int id  = ind[r];
        size_t ab_base = (size_t)b * (2 * HW);
        float wp = ab_p[ab_base + id] * 2.f * m;
        float hp = ab_p[ab_base + HW + id] * 2.f * m;
        float ap = (ang_p[(size_t)b * HW + id] - 90.f) * m;
        float xp = g_xy[0][b][t][0] * m, yp = g_xy[0][b][t][1] * m;
        float xt = g_xy[1][b][t][0] * m, yt = g_xy[1][b][t][1] * m;
        float wt = ab_t[r * 2] * 2.f * m, ht = ab_t[r * 2 + 1] * 2.f * m;
        float at = (ang_t[r] - 90.f) * m;
        loss = gwd_one(xp, yp, wp, hp, ap, xt, yt, wt, ht, at);
        mval = m;
    }
    for (int d = 16; d > 0; d >>= 1) {
        loss += __shfl_down_sync(0xffffffffu, loss, d);
        mval += __shfl_down_sync(0xffffffffu, mval, d);
    }
    __shared__ float rl[4], rm[4];
    if ((t & 31) == 0) { rl[t >> 5] = loss; rm[t >> 5] = mval; }
    __syncthreads();
    if (t == 0) {
        g_part[b][0] = rl[0] + rl[1] + rl[2] + rl[3];
        g_part[b][1] = rm[0] + rm[1] + rm[2] + rm[3];
    }
}

__global__ void finalize_kernel(float* __restrict__ out) {
    int t = threadIdx.x;  // 64 threads
    float l = g_part[t][0], m = g_part[t][1];
    for (int d = 16; d > 0; d >>= 1) {
        l += __shfl_down_sync(0xffffffffu, l, d);
        m += __shfl_down_sync(0xffffffffu, m, d);
    }
    __shared__ float sl[2], sm2[2];
    if ((t & 31) == 0) { sl[t >> 5] = l; sm2[t >> 5] = m; }
    __syncthreads();
    if (t == 0) out[0] = (sl[0] + sl[1]) / ((sm2[0] + sm2[1]) + 1e-8f);
}

extern "C" void kernel_launch(void* const* d_in, const int* in_sizes, int n_in,
                              void* d_out, int out_size) {
    const float* hm_p  = (const float*)d_in[0];
    const float* ab_p  = (const float*)d_in[1];
    const float* ang_p = (const float*)d_in[2];
    const float* hm_t  = (const float*)d_in[3];
    const float* ab_t  = (const float*)d_in[4];
    const float* ang_t = (const float*)d_in[5];
    const int*   ind   = (const int*)d_in[6];
    const int*   msk   = (const int*)d_in[7];
    float*       out   = (float*)d_out;

    const int dsmem = (CAP + KEEPC) * 8;   // 48 KB dynamic for refine
    cudaFuncSetAttribute(refine_kernel, cudaFuncAttributeMaxDynamicSharedMemorySize, dsmem);

    zero_kernel<<<NTB * NB2 / 4 / TPB, TPB>>>();
    hist_kernel<<<NTB * SLICES, TPB>>>(hm_p, hm_t);
    select_kernel<<<NTB, TPB>>>();
    collect_kernel<<<NTB * SLICES, TPB>>>(hm_p, hm_t);
    refine_kernel<<<NTB, 256, dsmem>>>();
    loss_kernel<<<BATCH, 128>>>(ab_p, ang_p, ab_t, ang_t, ind, msk);
    finalize_kernel<<<1, 64>>>(out);
}

// round 3
// speedup vs baseline: 1.6278x; 1.2851x over previous
#include <cuda_runtime.h>

#define HW     65536
#define BATCH  64
#define NTB    128
#define NK     100
#define SHIFT  19
#define NB2    8192          // 2^13 coarse bins on top 13 key bits
#define CAP    4096
#define KSAMP  64            // target sample survivor count (E[true] ~ 16*64)
#define TPB_T  1024
#define D2R    0.017453292519943295f

__device__ float g_xy[2][BATCH][NK][2];
__device__ float g_part[BATCH][2];

// order-preserving float->uint key (ascending)
__device__ __forceinline__ unsigned fkey(float f) {
    unsigned u = __float_as_uint(f);
    return u ^ ((unsigned)((int)u >> 31) | 0x80000000u);
}
__device__ __forceinline__ float inv_fkey(unsigned k) {
    unsigned u = (k & 0x80000000u) ? (k ^ 0x80000000u) : ~k;
    return __uint_as_float(u);
}

// Find bin b with (count in bins > b) < K <= (count in bins >= b). Block-collective.
__device__ void suffix_find(const unsigned* hist, int NB, unsigned K,
                            unsigned* s_ws, unsigned* s_bin, unsigned* s_above) {
    int tid  = threadIdx.x;
    int lane = tid & 31, warp = tid >> 5;
    int bpt  = (NB + TPB_T - 1) / TPB_T;
    int base = tid * bpt;
    unsigned p = 0;
    for (int j = 0; j < bpt; j++) {
        int b = base + j;
        if (b < NB) p += hist[b];
    }
    unsigned v = p;
    for (int d = 1; d < 32; d <<= 1) {
        unsigned o = __shfl_down_sync(0xffffffffu, v, d);
        if (lane + d < 32) v += o;
    }
    if (lane == 0) s_ws[warp] = v;
    __syncthreads();
    unsigned add = 0;
    for (int w = warp + 1; w < TPB_T / 32; w++) add += s_ws[w];
    unsigned sAfter = (v - p) + add;
    if (sAfter < K && sAfter + p >= K) {
        unsigned cum = sAfter;
        for (int j = bpt - 1; j >= 0; j--) {
            int b = base + j;
            if (b >= NB) continue;
            unsigned h = hist[b];
            if (cum + h >= K) { *s_bin = (unsigned)b; *s_above = cum; break; }
            cum += h;
        }
    }
    __syncthreads();
}

// One full collection pass: survivors (v >= thresh) staged into cand[] via
// ballot-aggregated shared atomics. Returns final count in *s_cnt (must be
// zeroed + synced by caller before the call; caller syncs after).
__device__ void collect_pass(const float4* __restrict__ src4, float thresh,
                             unsigned long long* cand, unsigned* s_cnt) {
    int tid = threadIdx.x, lane = tid & 31;
    unsigned lmask = (1u << lane) - 1u;
#pragma unroll
    for (int j = 0; j < HW / 4 / TPB_T; j++) {   // 16 iters
        int i4 = tid + j * TPB_T;
        float4 f = src4[i4];
        float v[4] = {f.x, f.y, f.z, f.w};
#pragma unroll
        for (int c = 0; c < 4; c++) {
            bool p = v[c] >= thresh;
            unsigned bal = __ballot_sync(0xffffffffu, p);
            if (bal) {
                int leader = __ffs(bal) - 1;
                unsigned basep = 0;
                if (lane == leader) basep = atomicAdd(s_cnt, (unsigned)__popc(bal));
                basep = __shfl_sync(0xffffffffu, basep, leader);
                if (p) {
                    unsigned pos = basep + (unsigned)__popc(bal & lmask);
                    if (pos < CAP) {
                        unsigned idx = (unsigned)(i4 * 4 + c);
                        cand[pos] = ((unsigned long long)fkey(v[c]) << 16) |
                                    (unsigned long long)(65535u - idx);
                    }
                }
            }
        }
    }
}

__global__ void __launch_bounds__(TPB_T)
topk_fused(const float* __restrict__ hm_p, const float* __restrict__ hm_t) {
    __shared__ __align__(16) unsigned sh_hist[NB2];     // 32KB; aliased by cand
    unsigned long long* cand = (unsigned long long*)sh_hist;  // 4096 entries
    __shared__ unsigned s_ws[TPB_T / 32];
    __shared__ unsigned s_bin, s_above, s_cnt;

    int tid = threadIdx.x;
    int tb  = blockIdx.x;
    const float* base = (tb >= BATCH) ? hm_t + (size_t)(tb - BATCH) * HW
                                      : hm_p + (size_t)tb * HW;
    const float4* src4 = (const float4*)base;

    // ---- Phase 1: sampled threshold (4096 samples, stride-16 float4) ----
    for (int i = tid; i < NB2; i += TPB_T) sh_hist[i] = 0;
    __syncthreads();
    {
        float4 f = src4[tid * 16];
        atomicAdd(&sh_hist[fkey(f.x) >> SHIFT], 1u);
        atomicAdd(&sh_hist[fkey(f.y) >> SHIFT], 1u);
        atomicAdd(&sh_hist[fkey(f.z) >> SHIFT], 1u);
        atomicAdd(&sh_hist[fkey(f.w) >> SHIFT], 1u);
    }
    __syncthreads();
    suffix_find(sh_hist, NB2, KSAMP, s_ws, &s_bin, &s_above);
    float thresh = inv_fkey(s_bin << SHIFT);

    // ---- Phase 2: single full pass, collect survivors ----
    if (tid == 0) s_cnt = 0;
    __syncthreads();            // hist reads complete -> cand alias safe
    collect_pass(src4, thresh, cand, &s_cnt);
    __syncthreads();
    unsigned Mc = s_cnt;

    // ---- Fallback: exact histogram if sampled threshold failed ----
    if (Mc < NK || Mc > CAP) {
        __syncthreads();
        for (int i = tid; i < NB2; i += TPB_T) sh_hist[i] = 0;
        __syncthreads();
#pragma unroll
        for (int j = 0; j < HW / 4 / TPB_T; j++) {
            float4 f = src4[tid + j * TPB_T];
            atomicAdd(&sh_hist[fkey(f.x) >> SHIFT], 1u);
            atomicAdd(&sh_hist[fkey(f.y) >> SHIFT], 1u);
            atomicAdd(&sh_hist[fkey(f.z) >> SHIFT], 1u);
            atomicAdd(&sh_hist[fkey(f.w) >> SHIFT], 1u);
        }
        __syncthreads();
        suffix_find(sh_hist, NB2, NK, s_ws, &s_bin, &s_above);
        thresh = inv_fkey(s_bin << SHIFT);
        if (tid == 0) s_cnt = 0;
        __syncthreads();
        collect_pass(src4, thresh, cand, &s_cnt);
        __syncthreads();
        Mc = s_cnt;
        if (Mc > CAP) Mc = CAP;   // R2-style truncation (ties beyond CAP)
    }

    // ---- Phase 3: exact bitonic sort of survivors (desc, jax tie order) ----
    unsigned P2 = 128;
    while (P2 < Mc) P2 <<= 1;
    for (unsigned i = Mc + tid; i < P2; i += TPB_T) cand[i] = 0ULL;
    __syncthreads();
    for (unsigned k = 2; k <= P2; k <<= 1) {
        for (unsigned j = k >> 1; j > 0; j >>= 1) {
            for (unsigned i = tid; i < P2; i += TPB_T) {
                unsigned ixj = i ^ j;
                if (ixj > i) {
                    unsigned long long a = cand[i], b = cand[ixj];
                    bool up = (i & k) == 0;
                    if (up ? (a < b) : (a > b)) { cand[i] = b; cand[ixj] = a; }
                }
            }
            __syncthreads();
        }
    }

    if (tid < NK) {
        unsigned idx = 65535u - (unsigned)(cand[tid] & 0xFFFFULL);
        int tensor = (tb >= BATCH) ? 1 : 0;
        g_xy[tensor][tb & 63][tid][0] = (float)(idx & 255u);   // x
        g_xy[tensor][tb & 63][tid][1] = (float)(idx >> 8);     // y
    }
}

__device__ __forceinline__ float gwd_one(float xp, float yp, float wp, float hp, float ap,
                                         float xt, float yt, float wt, float ht, float at) {
    wp = fminf(fmaxf(wp, 1e-7f), 1e7f);
    hp = fminf(fmaxf(hp, 1e-7f), 1e7f);
    wt = fminf(fmaxf(wt, 1e-7f), 1e7f);
    ht = fminf(fmaxf(ht, 1e-7f), 1e7f);
    float sp, cp, st, ct;
    sincosf(ap * D2R, &sp, &cp);
    sincosf(at * D2R, &st, &ct);
    float s1p = 0.5f * wp, s2p = 0.5f * hp, s1t = 0.5f * wt, s2t = 0.5f * ht;
    float dx = xp - xt, dy = yp - yt;
    float xyd = dx * dx + dy * dy;
    float q1p = s1p * s1p, q2p = s2p * s2p, q1t = s1t * s1t, q2t = s2t * s2t;
    float Ap = cp * cp * q1p + sp * sp * q2p;
    float Bp = cp * sp * (q1p - q2p);
    float Cp = sp * sp * q1p + cp * cp * q2p;
    float At = ct * ct * q1t + st * st * q2t;
    float Bt = ct * st * (q1t - q2t);
    float Ct = st * st * q1t + ct * ct * q2t;
    float whr  = q1p + q2p + q1t + q2t;
    float tr   = Ap * At + 2.f * Bp * Bt + Cp * Ct;
    float dets = s1p * s2p * s1t * s2t;
    whr -= 2.f * sqrtf(fmaxf(tr + 2.f * dets, 0.f));
    float d = fmaxf(xyd + whr, 0.f);
    d = log1pf(d);
    return 1.f - 1.f / (1.f + d);
}

__global__ void __launch_bounds__(128)
loss_kernel(const float* __restrict__ ab_p, const float* __restrict__ ang_p,
            const float* __restrict__ ab_t, const float* __restrict__ ang_t,
            const int* __restrict__ ind, const int* __restrict__ msk) {
    int b = blockIdx.x, t = threadIdx.x;
    float loss = 0.f, mval = 0.f;
    if (t < NK) {
        int r   = b * NK + t;
        float m = (float)msk[r];
        int id  = ind[r];
        size_t ab_base = (size_t)b * (2 * HW);
        float wp = ab_p[ab_base + id] * 2.f * m;
        float hp = ab_p[ab_base + HW + id] * 2.f * m;
        float ap = (ang_p[(size_t)b * HW + id] - 90.f) * m;
        float xp = g_xy[0][b][t][0] * m, yp = g_xy[0][b][t][1] * m;
        float xt = g_xy[1][b][t][0] * m, yt = g_xy[1][b][t][1] * m;
        float wt = ab_t[r * 2] * 2.f * m, ht = ab_t[r * 2 + 1] * 2.f * m;
        float at = (ang_t[r] - 90.f) * m;
        loss = gwd_one(xp, yp, wp, hp, ap, xt, yt, wt, ht, at);
        mval = m;
    }
    for (int d = 16; d > 0; d >>= 1) {
        loss += __shfl_down_sync(0xffffffffu, loss, d);
        mval += __shfl_down_sync(0xffffffffu, mval, d);
    }
    __shared__ float rl[4], rm[4];
    if ((t & 31) == 0) { rl[t >> 5] = loss; rm[t >> 5] = mval; }
    __syncthreads();
    if (t == 0) {
        g_part[b][0] = rl[0] + rl[1] + rl[2] + rl[3];
        g_part[b][1] = rm[0] + rm[1] + rm[2] + rm[3];
    }
}

__global__ void finalize_kernel(float* __restrict__ out) {
    int t = threadIdx.x;  // 64 threads
    float l = g_part[t][0], m = g_part[t][1];
    for (int d = 16; d > 0; d >>= 1) {
        l += __shfl_down_sync(0xffffffffu, l, d);
        m += __shfl_down_sync(0xffffffffu, m, d);
    }
    __shared__ float sl[2], sm2[2];
    if ((t & 31) == 0) { sl[t >> 5] = l; sm2[t >> 5] = m; }
    __syncthreads();
    if (t == 0) out[0] = (sl[0] + sl[1]) / ((sm2[0] + sm2[1]) + 1e-8f);
}

extern "C" void kernel_launch(void* const* d_in, const int* in_sizes, int n_in,
                              void* d_out, int out_size) {
    const float* hm_p  = (const float*)d_in[0];
    const float* ab_p  = (const float*)d_in[1];
    const float* ang_p = (const float*)d_in[2];
    const float* hm_t  = (const float*)d_in[3];
    const float* ab_t  = (const float*)d_in[4];
    const float* ang_t = (const float*)d_in[5];
    const int*   ind   = (const int*)d_in[6];
    const int*   msk   = (const int*)d_in[7];
    float*       out   = (float*)d_out;

    topk_fused<<<NTB, TPB_T>>>(hm_p, hm_t);
    loss_kernel<<<BATCH, 128>>>(ab_p, ang_p, ab_t, ang_t, ind, msk);
    finalize_kernel<<<1, 64>>>(out);
}

// round 4
// speedup vs baseline: 3.3437x; 2.0541x over previous
#include <cuda_runtime.h>

#define HW     65536
#define BATCH  64
#define NTB    128
#define NK     100
#define SHIFT  19
#define NB2    8192          // 2^13 coarse bins on top 13 key bits
#define CAP    4096
#define KEEP   1024
#define KSAMP  64            // target sample survivor count (E[true] ~ 16*64)
#define TPB_T  1024
#define D2R    0.017453292519943295f

__device__ float g_xy[2][BATCH][NK][2];
__device__ float g_part[BATCH][2];

// order-preserving float->uint key (ascending)
__device__ __forceinline__ unsigned fkey(float f) {
    unsigned u = __float_as_uint(f);
    return u ^ ((unsigned)((int)u >> 31) | 0x80000000u);
}
__device__ __forceinline__ float inv_fkey(unsigned k) {
    unsigned u = (k & 0x80000000u) ? (k ^ 0x80000000u) : ~k;
    return __uint_as_float(u);
}

// Find bin b with (count in bins > b) < K <= (count in bins >= b). Block-collective.
__device__ void suffix_find(const unsigned* hist, int NB, unsigned K,
                            unsigned* s_ws, unsigned* s_bin, unsigned* s_above) {
    int tid  = threadIdx.x;
    int lane = tid & 31, warp = tid >> 5;
    int bpt  = (NB + TPB_T - 1) / TPB_T;
    int base = tid * bpt;
    unsigned p = 0;
    for (int j = 0; j < bpt; j++) {
        int b = base + j;
        if (b < NB) p += hist[b];
    }
    unsigned v = p;
    for (int d = 1; d < 32; d <<= 1) {
        unsigned o = __shfl_down_sync(0xffffffffu, v, d);
        if (lane + d < 32) v += o;
    }
    if (lane == 0) s_ws[warp] = v;
    __syncthreads();
    unsigned add = 0;
    for (int w = warp + 1; w < TPB_T / 32; w++) add += s_ws[w];
    unsigned sAfter = (v - p) + add;
    if (sAfter < K && sAfter + p >= K) {
        unsigned cum = sAfter;
        for (int j = bpt - 1; j >= 0; j--) {
            int b = base + j;
            if (b >= NB) continue;
            unsigned h = hist[b];
            if (cum + h >= K) { *s_bin = (unsigned)b; *s_above = cum; break; }
            cum += h;
        }
    }
    __syncthreads();
}

// Ballot-free collection: survivors are rare, so each does its own shared atomic.
__device__ void collect_pass(const float4* __restrict__ src4, float thresh,
                             unsigned long long* cand, unsigned* s_cnt) {
    int tid = threadIdx.x;
#pragma unroll
    for (int j = 0; j < HW / 4 / TPB_T; j++) {   // 16 iters
        int i4 = tid + j * TPB_T;
        float4 f = src4[i4];
        float v[4] = {f.x, f.y, f.z, f.w};
#pragma unroll
        for (int c = 0; c < 4; c++) {
            if (v[c] >= thresh) {
                unsigned pos = atomicAdd(s_cnt, 1u);
                if (pos < CAP) {
                    unsigned idx = (unsigned)(i4 * 4 + c);
                    cand[pos] = ((unsigned long long)fkey(v[c]) << 16) |
                                (unsigned long long)(65535u - idx);
                }
            }
        }
    }
}

__global__ void __launch_bounds__(TPB_T)
topk_fused(const float* __restrict__ hm_p, const float* __restrict__ hm_t) {
    __shared__ __align__(16) unsigned sh_hist[NB2];           // 32KB; aliased by cand
    unsigned long long* cand = (unsigned long long*)sh_hist;  // 4096 entries
    __shared__ __align__(16) unsigned long long sk[KEEP];     // 8KB keep buffer
    __shared__ unsigned rh[256];
    __shared__ unsigned s_ws[TPB_T / 32];
    __shared__ unsigned s_bin, s_above, s_cnt, s_kcnt;

    int tid = threadIdx.x;
    int tb  = blockIdx.x;
    const float* base = (tb >= BATCH) ? hm_t + (size_t)(tb - BATCH) * HW
                                      : hm_p + (size_t)tb * HW;
    const float4* src4 = (const float4*)base;

    // ---- Phase 1: sampled threshold (4096 samples, stride-16 float4) ----
    for (int i = tid; i < NB2; i += TPB_T) sh_hist[i] = 0;
    __syncthreads();
    {
        float4 f = src4[tid * 16];
        atomicAdd(&sh_hist[fkey(f.x) >> SHIFT], 1u);
        atomicAdd(&sh_hist[fkey(f.y) >> SHIFT], 1u);
        atomicAdd(&sh_hist[fkey(f.z) >> SHIFT], 1u);
        atomicAdd(&sh_hist[fkey(f.w) >> SHIFT], 1u);
    }
    __syncthreads();
    suffix_find(sh_hist, NB2, KSAMP, s_ws, &s_bin, &s_above);
    unsigned b0 = s_bin;
    float thresh = inv_fkey(b0 << SHIFT);

    // ---- Phase 2: single full pass, collect survivors ----
    if (tid == 0) s_cnt = 0;
    __syncthreads();            // hist reads complete -> cand alias safe
    collect_pass(src4, thresh, cand, &s_cnt);
    __syncthreads();
    unsigned Mc = s_cnt;

    // ---- Fallback: exact histogram if sampled threshold failed ----
    if (Mc < NK || Mc > CAP) {
        __syncthreads();
        for (int i = tid; i < NB2; i += TPB_T) sh_hist[i] = 0;
        __syncthreads();
#pragma unroll
        for (int j = 0; j < HW / 4 / TPB_T; j++) {
            float4 f = src4[tid + j * TPB_T];
            atomicAdd(&sh_hist[fkey(f.x) >> SHIFT], 1u);
            atomicAdd(&sh_hist[fkey(f.y) >> SHIFT], 1u);
            atomicAdd(&sh_hist[fkey(f.z) >> SHIFT], 1u);
            atomicAdd(&sh_hist[fkey(f.w) >> SHIFT], 1u);
        }
        __syncthreads();
        suffix_find(sh_hist, NB2, NK, s_ws, &s_bin, &s_above);
        b0 = s_bin;
        thresh = inv_fkey(b0 << SHIFT);
        if (tid == 0) s_cnt = 0;
        __syncthreads();
        collect_pass(src4, thresh, cand, &s_cnt);
        __syncthreads();
        Mc = s_cnt;
        if (Mc > CAP) Mc = CAP;   // truncation only in pathological tie storms
    }

    // ---- Phase 3: refine to ~NK+eps using next 8 key bits (clamped offset) ----
    if (tid < 256) rh[tid] = 0;
    if (tid == 0) s_kcnt = 0;
    __syncthreads();
    unsigned b0base = b0 << 8;
    for (unsigned i = tid; i < Mc; i += TPB_T) {
        unsigned key = (unsigned)(cand[i] >> 16);
        unsigned off = (key >> (SHIFT - 8)) - b0base;   // >= 0 by construction
        if (off > 255u) off = 255u;
        atomicAdd(&rh[off], 1u);
    }
    __syncthreads();
    suffix_find(rh, 256, NK, s_ws, &s_bin, &s_above);
    unsigned r0 = s_bin;
    for (unsigned i = tid; i < Mc; i += TPB_T) {
        unsigned long long e = cand[i];
        unsigned key = (unsigned)(e >> 16);
        unsigned off = (key >> (SHIFT - 8)) - b0base;
        if (off > 255u) off = 255u;
        if (off >= r0) {
            unsigned p = atomicAdd(&s_kcnt, 1u);
            if (p < KEEP) sk[p] = e;
        }
    }
    __syncthreads();
    unsigned Mk = s_kcnt;
    bool big = (Mk > KEEP);     // pathological: sort full cand buffer instead
    unsigned long long* buf = big ? cand : sk;
    unsigned n = big ? Mc : Mk;

    // ---- Phase 4: exact bitonic sort (desc on (key, 65535-idx) => jax ties) ----
    unsigned P2 = 128;
    while (P2 < n) P2 <<= 1;
    for (unsigned i = n + tid; i < P2; i += TPB_T) buf[i] = 0ULL;
    __syncthreads();
    for (unsigned k = 2; k <= P2; k <<= 1) {
        for (unsigned j = k >> 1; j > 0; j >>= 1) {
            for (unsigned i = tid; i < P2; i += TPB_T) {
                unsigned ixj = i ^ j;
                if (ixj > i) {
                    unsigned long long a = buf[i], b = buf[ixj];
                    bool up = (i & k) == 0;
                    if (up ? (a < b) : (a > b)) { buf[i] = b; buf[ixj] = a; }
                }
            }
            __syncthreads();
        }
    }

    if (tid < NK) {
        unsigned idx = 65535u - (unsigned)(buf[tid] & 0xFFFFULL);
        int tensor = (tb >= BATCH) ? 1 : 0;
        g_xy[tensor][tb & 63][tid][0] = (float)(idx & 255u);   // x
        g_xy[tensor][tb & 63][tid][1] = (float)(idx >> 8);     // y
    }
}

__device__ __forceinline__ float gwd_one(float xp, float yp, float wp, float hp, float ap,
                                         float xt, float yt, float wt, float ht, float at) {
    wp = fminf(fmaxf(wp, 1e-7f), 1e7f);
    hp = fminf(fmaxf(hp, 1e-7f), 1e7f);
    wt = fminf(fmaxf(wt, 1e-7f), 1e7f);
    ht = fminf(fmaxf(ht, 1e-7f), 1e7f);
    float sp, cp, st, ct;
    sincosf(ap * D2R, &sp, &cp);
    sincosf(at * D2R, &st, &ct);
    float s1p = 0.5f * wp, s2p = 0.5f * hp, s1t = 0.5f * wt, s2t = 0.5f * ht;
    float dx = xp - xt, dy = yp - yt;
    float xyd = dx * dx + dy * dy;
    float q1p = s1p * s1p, q2p = s2p * s2p, q1t = s1t * s1t, q2t = s2t * s2t;
    float Ap = cp * cp * q1p + sp * sp * q2p;
    float Bp = cp * sp * (q1p - q2p);
    float Cp = sp * sp * q1p + cp * cp * q2p;
    float At = ct * ct * q1t + st * st * q2t;
    float Bt = ct * st * (q1t - q2t);
    float Ct = st * st * q1t + ct * ct * q2t;
    float whr  = q1p + q2p + q1t + q2t;
    float tr   = Ap * At + 2.f * Bp * Bt + Cp * Ct;
    float dets = s1p * s2p * s1t * s2t;
    whr -= 2.f * sqrtf(fmaxf(tr + 2.f * dets, 0.f));
    float d = fmaxf(xyd + whr, 0.f);
    d = log1pf(d);
    return 1.f - 1.f / (1.f + d);
}

__global__ void __launch_bounds__(128)
loss_kernel(const float* __restrict__ ab_p, const float* __restrict__ ang_p,
            const float* __restrict__ ab_t, const float* __restrict__ ang_t,
            const int* __restrict__ ind, const int* __restrict__ msk) {
    int b = blockIdx.x, t = threadIdx.x;
    float loss = 0.f, mval = 0.f;
    if (t < NK) {
        int r   = b * NK + t;
        float m = (float)msk[r];
        int id  = ind[r];
        size_t ab_base = (size_t)b * (2 * HW);
        float wp = ab_p[ab_base + id] * 2.f * m;
        float hp = ab_p[ab_base + HW + id] * 2.f * m;
        float ap = (ang_p[(size_t)b * HW + id] - 90.f) * m;
        float xp = g_xy[0][b][t][0] * m, yp = g_xy[0][b][t][1] * m;
        float xt = g_xy[1][b][t][0] * m, yt = g_xy[1][b][t][1] * m;
        float wt = ab_t[r * 2] * 2.f * m, ht = ab_t[r * 2 + 1] * 2.f * m;
        float at = (ang_t[r] - 90.f) * m;
        loss = gwd_one(xp, yp, wp, hp, ap, xt, yt, wt, ht, at);
        mval = m;
    }
    for (int d = 16; d > 0; d >>= 1) {
        loss += __shfl_down_sync(0xffffffffu, loss, d);
        mval += __shfl_down_sync(0xffffffffu, mval, d);
    }
    __shared__ float rl[4], rm[4];
    if ((t & 31) == 0) { rl[t >> 5] = loss; rm[t >> 5] = mval; }
    __syncthreads();
    if (t == 0) {
        g_part[b][0] = rl[0] + rl[1] + rl[2] + rl[3];
        g_part[b][1] = rm[0] + rm[1] + rm[2] + rm[3];
    }
}

__global__ void finalize_kernel(float* __restrict__ out) {
    int t = threadIdx.x;  // 64 threads
    float l = g_part[t][0], m = g_part[t][1];
    for (int d = 16; d > 0; d >>= 1) {
        l += __shfl_down_sync(0xffffffffu, l, d);
        m += __shfl_down_sync(0xffffffffu, m, d);
    }
    __shared__ float sl[2], sm2[2];
    if ((t & 31) == 0) { sl[t >> 5] = l; sm2[t >> 5] = m; }
    __syncthreads();
    if (t == 0) out[0] = (sl[0] + sl[1]) / ((sm2[0] + sm2[1]) + 1e-8f);
}

extern "C" void kernel_launch(void* const* d_in, const int* in_sizes, int n_in,
                              void* d_out, int out_size) {
    const float* hm_p  = (const float*)d_in[0];
    const float* ab_p  = (const float*)d_in[1];
    const float* ang_p = (const float*)d_in[2];
    const float* hm_t  = (const float*)d_in[3];
    const float* ab_t  = (const float*)d_in[4];
    const float* ang_t = (const float*)d_in[5];
    const int*   ind   = (const int*)d_in[6];
    const int*   msk   = (const int*)d_in[7];
    float*       out   = (float*)d_out;

    topk_fused<<<NTB, TPB_T>>>(hm_p, hm_t);
    loss_kernel<<<BATCH, 128>>>(ab_p, ang_p, ab_t, ang_t, ind, msk);
    finalize_kernel<<<1, 64>>>(out);
}